// round 15
// baseline (speedup 1.0000x reference)
#include <cuda_runtime.h>
#include <cuda_bf16.h>
#include <math.h>
#include <stdint.h>

// Problem constants
constexpr int BB = 2;
constexpr int QQ = 2048;
constexpr int MM = 2048;
constexpr int HH = 16;
constexpr int HID = 1024;      // H*D
constexpr int KK = MM + QQ;    // 4096

// ---------------- tf32 mma helpers ------------------------------------------
__device__ __forceinline__ uint32_t f2tf(float f)
{
    uint32_t r;
    asm("cvt.rna.tf32.f32 %0, %1;" : "=r"(r) : "f"(f));
    return r;
}
__device__ __forceinline__ float f2tff(float f)
{
    return __uint_as_float(f2tf(f));
}
__device__ __forceinline__ void mma_tf32(float4& c, const uint32_t* a, const uint32_t* b)
{
    asm volatile("mma.sync.aligned.m16n8k8.row.col.f32.tf32.tf32.f32 "
                 "{%0,%1,%2,%3}, {%4,%5,%6,%7}, {%8,%9}, {%0,%1,%2,%3};\n"
                 : "+f"(c.x), "+f"(c.y), "+f"(c.z), "+f"(c.w)
                 : "r"(a[0]), "r"(a[1]), "r"(a[2]), "r"(a[3]),
                   "r"(b[0]), "r"(b[1]));
}
// ldmatrix x4: thread T gets 4B at (row T/4, byte 4*(T%4)) of each 8x16B tile.
__device__ __forceinline__ void ldsm_x4(uint32_t& r0, uint32_t& r1,
                                        uint32_t& r2, uint32_t& r3, uint32_t saddr)
{
    asm volatile("ldmatrix.sync.aligned.m8n8.x4.shared.b16 {%0,%1,%2,%3}, [%4];\n"
                 : "=r"(r0), "=r"(r1), "=r"(r2), "=r"(r3) : "r"(saddr));
}
__device__ __forceinline__ void cpa16(void* s, const void* g)   // L1-bypass (streaming)
{
    uint32_t sa = (uint32_t)__cvta_generic_to_shared(s);
    asm volatile("cp.async.cg.shared.global [%0], [%1], 16;\n" :: "r"(sa), "l"(g));
}
__device__ __forceinline__ void cpa16ca(void* s, const void* g) // L1-allocating
{
    uint32_t sa = (uint32_t)__cvta_generic_to_shared(s);
    asm volatile("cp.async.ca.shared.global [%0], [%1], 16;\n" :: "r"(sa), "l"(g));
}
__device__ __forceinline__ void cpa16ca_z(void* s, const void* g, int nbytes)
{
    uint32_t sa = (uint32_t)__cvta_generic_to_shared(s);
    asm volatile("cp.async.ca.shared.global [%0], [%1], 16, %2;\n"
                 :: "r"(sa), "l"(g), "r"(nbytes));
}
#define CP_COMMIT()  asm volatile("cp.async.commit_group;\n" ::: "memory")
#define CP_WAIT(N)   asm volatile("cp.async.wait_group %0;\n" :: "n"(N) : "memory")
__device__ __forceinline__ float ex2_approx(float x)
{
    float r;
    asm("ex2.approx.f32 %0, %1;" : "=f"(r) : "f"(x));
    return r;
}

// ---------------- scratch (device globals; no allocations allowed) ----------
__device__ float g_kvln[(size_t)BB * KK * HID];
__device__ float g_qln [(size_t)BB * QQ * HID];
__device__ float g_pe  [(size_t)KK * HID];
__device__ float g_Qp  [(size_t)BB * QQ * HID];
__device__ float g_Kp  [(size_t)BB * KK * HID];
__device__ float g_Vp  [(size_t)BB * KK * HID];
__device__ float g_Rel [(size_t)KK * HID];
__device__ float g_attn[(size_t)BB * QQ * HID];
__device__ float g_Wtf [(size_t)5 * HID * HID];   // tf32-rounded weight copies

// ---------------- tf32 rounding prepass (weights) ----------------------------
__global__ __launch_bounds__(256)
void round_tf32_kernel(const float* __restrict__ src, float* __restrict__ dst)
{
    int i = blockIdx.x * 256 + threadIdx.x;      // float4 index
    float4 v = ((const float4*)src)[i];
    ((float4*)dst)[i] = make_float4(f2tff(v.x), f2tff(v.y), f2tff(v.z), f2tff(v.w));
}

// ---------------- LayerNorm over rows of length 1024 (tf32-rounded out) -----
__device__ __forceinline__ void ln_row_1024(const float* __restrict__ src,
                                            float* __restrict__ dst,
                                            const float* __restrict__ gamma,
                                            const float* __restrict__ beta)
{
    __shared__ float red[16];
    int tid = threadIdx.x;                    // 256 threads, 4 floats each
    float4 v = ((const float4*)src)[tid];
    float s1 = v.x + v.y + v.z + v.w;
    float s2 = v.x*v.x + v.y*v.y + v.z*v.z + v.w*v.w;
#pragma unroll
    for (int off = 16; off; off >>= 1) {
        s1 += __shfl_xor_sync(0xffffffffu, s1, off);
        s2 += __shfl_xor_sync(0xffffffffu, s2, off);
    }
    if ((tid & 31) == 0) { red[tid >> 5] = s1; red[8 + (tid >> 5)] = s2; }
    __syncthreads();
    if (tid == 0) {
        float a = 0.f, b = 0.f;
#pragma unroll
        for (int i = 0; i < 8; i++) { a += red[i]; b += red[8 + i]; }
        float mu  = a * (1.0f / 1024.0f);
        float var = b * (1.0f / 1024.0f) - mu * mu;
        red[0] = mu;
        red[1] = rsqrtf(var + 1e-3f);
    }
    __syncthreads();
    float mu = red[0], sc = red[1];
    float4 g  = ((const float4*)gamma)[tid];
    float4 bb = ((const float4*)beta)[tid];
    float4 o;
    o.x = f2tff((v.x - mu) * sc * g.x + bb.x);
    o.y = f2tff((v.y - mu) * sc * g.y + bb.y);
    o.z = f2tff((v.z - mu) * sc * g.z + bb.z);
    o.w = f2tff((v.w - mu) * sc * g.w + bb.w);
    ((float4*)dst)[tid] = o;
}

__global__ __launch_bounds__(256)
void ln_kv_kernel(const float* __restrict__ mem, const float* __restrict__ qry,
                  const float* __restrict__ gamma, const float* __restrict__ beta,
                  float* __restrict__ out)
{
    int row = blockIdx.x;
    int b = row / KK, r = row % KK;
    const float* src = (r < MM) ? (mem + ((size_t)b * MM + r) * HID)
                                : (qry + ((size_t)b * QQ + (r - MM)) * HID);
    ln_row_1024(src, out + (size_t)row * HID, gamma, beta);
}

__global__ __launch_bounds__(256)
void ln_q_kernel(const float* __restrict__ qry,
                 const float* __restrict__ gamma, const float* __restrict__ beta,
                 float* __restrict__ out)
{
    int row = blockIdx.x;
    ln_row_1024(qry + (size_t)row * HID, out + (size_t)row * HID, gamma, beta);
}

// ---------------- sinusoidal relative position embedding (fast MUFU) --------
__global__ __launch_bounds__(512)
void posemb_kernel(float* __restrict__ pe)
{
    int j = blockIdx.x;                        // 0 .. KK-1
    int i = threadIdx.x;                       // 0 .. 511
    float pos = (float)(KK - 1 - j);
    const float c2 = -13.287712379549449f / 512.0f;
    float invf = ex2_approx(c2 * (float)i);
    float ang  = pos * invf;
    float k = rintf(ang * 0.15915494309189535f);
    float a = fmaf(k, -6.2831854820251465f, ang);
    a = fmaf(k, 1.7484555e-7f, a);
    float s, cc;
    __sincosf(a, &s, &cc);
    pe[(size_t)j * HID + i]       = f2tff(s);
    pe[(size_t)j * HID + 512 + i] = f2tff(cc);
}

// ---------------- tf32 SGEMM: C[M,1024] = A[M,1024]*B[1024,1024] ------------
// Inputs pre-rounded to tf32; A-fragments via ldmatrix.
constexpr int GA_STRIDE = 20;
constexpr int GB_STRIDE = 136;
constexpr int GA_BUF = 128 * GA_STRIDE;   // 2560
constexpr int GB_BUF = 16 * GB_STRIDE;    // 2176
constexpr int GEMM_SMEM_BYTES = 3 * (GA_BUF + GB_BUF) * 4;   // 56,832 B

__global__ __launch_bounds__(256, 2)
void sgemm_tf32(const float* __restrict__ A, const float* __restrict__ B,
                float* __restrict__ C, int roundC)
{
    extern __shared__ float gsm[];
    float* sA = gsm;                  // 3 x [128][20]
    float* sB = gsm + 3 * GA_BUF;     // 3 x [16][136]
    const int tid = threadIdx.x;
    const int lane = tid & 31, wid = tid >> 5;
    const int g = lane >> 2, tg = lane & 3;
    const int quad = lane >> 3, r8 = lane & 7;
    const int qr = quad & 1, qc = quad >> 1;
    const int wm = (wid & 1) * 64, wn = (wid >> 1) * 32;
    const int row0 = blockIdx.y * 128, col0 = blockIdx.x * 128;
    const uint32_t gs32 = (uint32_t)__cvta_generic_to_shared(gsm);

    // ldmatrix lane offsets for A fragments (bytes)
    uint32_t afOff[4];
#pragma unroll
    for (int mf = 0; mf < 4; mf++)
        afOff[mf] = ((wm + mf * 16 + qr * 8 + r8) * GA_STRIDE + qc * 4) * 4;

    const int af4a = tid,        af4b = tid + 256;
    const int ar_a = af4a >> 2,  ac_a = (af4a & 3) << 2;
    const int ar_b = af4b >> 2,  ac_b = (af4b & 3) << 2;
    const int br_a = af4a >> 5,  bc_a = (af4a & 31) << 2;
    const int br_b = af4b >> 5,  bc_b = (af4b & 31) << 2;

    auto issue = [&](int buf, int k0) {
        float* a = sA + buf * GA_BUF;
        float* bfp = sB + buf * GB_BUF;
        cpa16(&a[ar_a * GA_STRIDE + ac_a], &A[(size_t)(row0 + ar_a) * 1024 + k0 + ac_a]);
        cpa16(&a[ar_b * GA_STRIDE + ac_b], &A[(size_t)(row0 + ar_b) * 1024 + k0 + ac_b]);
        cpa16(&bfp[br_a * GB_STRIDE + bc_a], &B[(size_t)(k0 + br_a) * 1024 + col0 + bc_a]);
        cpa16(&bfp[br_b * GB_STRIDE + bc_b], &B[(size_t)(k0 + br_b) * 1024 + col0 + bc_b]);
    };

    issue(0, 0);
    CP_COMMIT();
    issue(1, 16);
    CP_COMMIT();

    float4 acc[4][4];
#pragma unroll
    for (int i = 0; i < 4; i++)
#pragma unroll
        for (int j = 0; j < 4; j++) acc[i][j] = make_float4(0.f, 0.f, 0.f, 0.f);

    for (int it = 0; it < 64; it++) {
        CP_WAIT(1);
        __syncthreads();
        if (it + 2 < 64) issue((it + 2) % 3, (it + 2) * 16);
        CP_COMMIT();

        const uint32_t sA32 = gs32 + (uint32_t)((it % 3) * GA_BUF) * 4;
        const float* bs = sB + (it % 3) * GB_BUF;
#pragma unroll
        for (int kk = 0; kk < 16; kk += 8) {
            uint32_t af[4][4], bf[4][2];
#pragma unroll
            for (int mf = 0; mf < 4; mf++)
                ldsm_x4(af[mf][0], af[mf][1], af[mf][2], af[mf][3],
                        sA32 + afOff[mf] + kk * 4);
#pragma unroll
            for (int nf = 0; nf < 4; nf++) {
                int n = wn + nf * 8;
                bf[nf][0] = __float_as_uint(bs[(kk + tg) * GB_STRIDE + n + g]);
                bf[nf][1] = __float_as_uint(bs[(kk + tg + 4) * GB_STRIDE + n + g]);
            }
#pragma unroll
            for (int mf = 0; mf < 4; mf++)
#pragma unroll
                for (int nf = 0; nf < 4; nf++)
                    mma_tf32(acc[mf][nf], af[mf], bf[nf]);
        }
    }
    if (roundC) {
#pragma unroll
        for (int mf = 0; mf < 4; mf++)
#pragma unroll
            for (int nf = 0; nf < 4; nf++) {
                int r = row0 + wm + mf * 16 + g;
                int c = col0 + wn + nf * 8 + 2 * tg;
                *(float2*)&C[(size_t)r * 1024 + c] =
                    make_float2(f2tff(acc[mf][nf].x), f2tff(acc[mf][nf].y));
                *(float2*)&C[(size_t)(r + 8) * 1024 + c] =
                    make_float2(f2tff(acc[mf][nf].z), f2tff(acc[mf][nf].w));
            }
    } else {
#pragma unroll
        for (int mf = 0; mf < 4; mf++)
#pragma unroll
            for (int nf = 0; nf < 4; nf++) {
                int r = row0 + wm + mf * 16 + g;
                int c = col0 + wn + nf * 8 + 2 * tg;
                *(float2*)&C[(size_t)r * 1024 + c] = make_float2(acc[mf][nf].x, acc[mf][nf].y);
                *(float2*)&C[(size_t)(r + 8) * 1024 + c] = make_float2(acc[mf][nf].z, acc[mf][nf].w);
            }
    }
}

// ---------------- fused relative attention (tf32 mma, banded BD, ldmatrix) --
// grid: (Q/64, B*H); 256 threads, 8 warps.
// S^T = K*Qw^T, BD^T = Rel*Qw^T banded to j+q in [63,126], O^T = V^T*P^T.
// uQ stored [q][d], uPT stored [q][key] (n-major) -> B-frags via ldmatrix.
constexpr int AT_SQ  = 0;       // Qw  [64 q][68 d]   tf32
constexpr int AT_SK  = 4352;    // K   [64 k][68 d]   tf32
constexpr int AT_SV  = 8704;    // V   [64 k][72 d]   tf32
constexpr int AT_SR  = 13312;   // Rel [128 j][68 d]  tf32 / BD^T f32 (alias)
constexpr int AT_SPT = 22016;   // P   [64 q][68 key] tf32
constexpr int AT_SB1 = 26368;   // bd1 halves [256] f32
constexpr int AT_SDL = 26624;   // dl   [64]  f32
constexpr int AT_SRM = 26688;   // lm red [4][64]
constexpr int AT_SRF = 26944;   // lf red [4][64]
constexpr int AT_SIV = 27200;   // inv  [64]
constexpr int AT_TOT = 27264;
constexpr int ATTN_SMEM_BYTES = AT_TOT * 4;     // 109,056 B -> 2 CTAs/SM

__global__ __launch_bounds__(256, 2)
void attn_tf32(const float* __restrict__ Qp, const float* __restrict__ Kp,
               const float* __restrict__ Vp, const float* __restrict__ Rel,
               const float* __restrict__ rwb, const float* __restrict__ rrb,
               const float* __restrict__ span, float* __restrict__ Out)
{
    extern __shared__ float sm[];
    uint32_t* uQ  = (uint32_t*)(sm + AT_SQ);
    uint32_t* uK  = (uint32_t*)(sm + AT_SK);
    uint32_t* uV  = (uint32_t*)(sm + AT_SV);
    uint32_t* uR  = (uint32_t*)(sm + AT_SR);
    float*   sBDT = sm + AT_SR;                  // alias over Rel
    uint32_t* uPT = (uint32_t*)(sm + AT_SPT);
    float* sB1 = sm + AT_SB1;
    float* sDl = sm + AT_SDL;
    float* sRM = sm + AT_SRM;
    float* sRF = sm + AT_SRF;
    float* sIv = sm + AT_SIV;
    const uint32_t sm32 = (uint32_t)__cvta_generic_to_shared(sm);
    const uint32_t uQ32 = sm32 + AT_SQ * 4;
    const uint32_t uK32 = sm32 + AT_SK * 4;
    const uint32_t uR32 = sm32 + AT_SR * 4;
    const uint32_t uPT32 = sm32 + AT_SPT * 4;

    const int tid = threadIdx.x;
    const int lane = tid & 31, wid = tid >> 5;
    const int g = lane >> 2, tg = lane & 3;
    const int quad = lane >> 3, r8 = lane & 7;
    const int qr = quad & 1, qc = quad >> 1;
    const int wm = wid & 3;            // key/d strip (x16) for AD / PV
    const int wn = wid >> 2;           // q half (x32)
    // BD band assignment: strip sB = 7-wid aligns bd q-range with sf q-range
    const int sB  = 7 - wid;
    const int nf_lo = max(0, 6 - 2 * sB);
    const int nf_hi = min(7, 15 - 2 * sB);
    const int lo2 = min(nf_lo, wn * 4);
    const int hi2 = max(nf_hi, wn * 4 + 3);
    // big-work CTAs launch first
    const int qt = (int)gridDim.x - 1 - (int)blockIdx.x;
    const int q0 = qt * 64;
    const int b = blockIdx.y >> 4, h = blockIdx.y & 15;
    const float spanv = span[h];

    // ldmatrix lane offsets (bytes)
    // A-frag (rows=m dim, cols=k dim): row-half=qr, col-half=qc
    const uint32_t akOff = uK32 + ((wm * 16 + qr * 8 + r8) * 68 + qc * 4) * 4;
    const uint32_t arOff = uR32 + ((sB * 16 + qr * 8 + r8) * 68 + qc * 4) * 4;
    // B-frag pairs (rows=n dim, cols=k dim): row-pair=qc, col-half=qr
    uint32_t bqOff[4], bpOff[2];
#pragma unroll
    for (int p = 0; p < 4; p++)
        bqOff[p] = uQ32 + (((2 * p + qc) * 8 + r8) * 68 + qr * 4) * 4;
#pragma unroll
    for (int p = 0; p < 2; p++)
        bpOff[p] = uPT32 + ((wn * 32 + (2 * p + qc) * 8 + r8) * 68 + qr * 4) * 4;

    // staging issuers (cp.async.ca — L1-allocating; all operands pre-rounded)
    auto issueK = [&](int k0s) {
#pragma unroll
        for (int idx = tid; idx < 1024; idx += 256) {
            int kk = idx >> 4, d4 = (idx & 15) << 2;
            cpa16ca(&uK[kk * 68 + d4],
                    &Kp[((size_t)(b * KK + k0s + kk)) * HID + h * 64 + d4]);
        }
    };
    auto issueV = [&](int k0s) {
#pragma unroll
        for (int idx = tid; idx < 1024; idx += 256) {
            int kk = idx >> 4, d4 = (idx & 15) << 2;
            cpa16ca(&uV[kk * 72 + d4],
                    &Vp[((size_t)(b * KK + k0s + kk)) * HID + h * 64 + d4]);
        }
    };
    auto issueR = [&](int k0s) {
        int jb = k0s + (QQ - 1) - (q0 + 63);
#pragma unroll
        for (int idx = tid; idx < 2048; idx += 256) {
            int jj = idx >> 4, d4 = (idx & 15) << 2;
            int j = jb + jj;
            bool ok = (j < KK);
            cpa16ca_z(&uR[jj * 68 + d4],
                      ok ? &Rel[(size_t)j * HID + h * 64 + d4] : (const float*)Rel,
                      ok ? 16 : 0);
        }
    };

    if (tid < 64) sDl[tid] = rrb[h * 64 + tid] - rwb[h * 64 + tid];

    // prologue: K(0), R(0) in flight
    issueK(0); CP_COMMIT();
    issueR(0); CP_COMMIT();

    // stage Qw = q + r_w_bias, tf32, layout [q][68] (once per CTA)
    for (int idx = tid; idx < 1024; idx += 256) {
        int qq = idx >> 4, d4 = (idx & 15) << 2;
        float4 qv = *(const float4*)&Qp[((size_t)(b * QQ + q0 + qq)) * HID + h * 64 + d4];
        float4 wb = *(const float4*)&rwb[h * 64 + d4];
        *(uint4*)&uQ[qq * 68 + d4] =
            make_uint4(f2tf(qv.x + wb.x), f2tf(qv.y + wb.y),
                       f2tf(qv.z + wb.z), f2tf(qv.w + wb.w));
    }

    float4 o[4];
#pragma unroll
    for (int i = 0; i < 4; i++) o[i] = make_float4(0.f, 0.f, 0.f, 0.f);
    float lfp[8], lmp[8];
#pragma unroll
    for (int i = 0; i < 8; i++) { lfp[i] = 0.f; lmp[i] = 0.f; }

    const int ntiles = 33 + qt;
    for (int t = 0; t < ntiles; t++) {
        const int k0 = t * 64;
        const int k0n = min(k0 + 64, KK - 64);  // clamped prefetch target

        __syncthreads();               // PV(t-1) complete; uV free (Q stage at t=0)
        issueV(k0); CP_COMMIT();       // groups: [K(t), R(t), V(t)]
        CP_WAIT(1);                    // K(t), R(t) arrived (this thread)
        __syncthreads();               // ... visible to all threads

        // bd1[j] = sum_d Rel[j][d] * dl[d]
        {
            int j = tid >> 1, half = tid & 1;
            const float* rr = (const float*)&uR[j * 68 + half * 32];
            const float* dd = &sDl[half * 32];
            float s = 0.f;
#pragma unroll
            for (int d4 = 0; d4 < 32; d4 += 4) {
                float4 r4 = *(const float4*)&rr[d4];
                float4 dl4 = *(const float4*)&dd[d4];
                s += r4.x * dl4.x + r4.y * dl4.y + r4.z * dl4.z + r4.w * dl4.w;
            }
            sB1[tid] = s;
        }

        // AD^T + banded BD^T mma (shared B-operand = Qw; ldmatrix frags)
        float4 sf[4];
        float4 bdf[8];
#pragma unroll
        for (int i = 0; i < 4; i++) sf[i] = make_float4(0.f, 0.f, 0.f, 0.f);
#pragma unroll
        for (int i = 0; i < 8; i++) bdf[i] = make_float4(0.f, 0.f, 0.f, 0.f);
        {
            uint32_t akA = akOff, arA = arOff;
            uint32_t bqA[4] = {bqOff[0], bqOff[1], bqOff[2], bqOff[3]};
#pragma unroll
            for (int ks = 0; ks < 64; ks += 8) {
                uint32_t bq[8][2];
#pragma unroll
                for (int p = 0; p < 4; p++) {
                    if (2 * p + 1 >= lo2 && 2 * p <= hi2)
                        ldsm_x4(bq[2 * p][0], bq[2 * p][1],
                                bq[2 * p + 1][0], bq[2 * p + 1][1], bqA[p]);
                    bqA[p] += 32;
                }
                uint32_t ak[4], ar[4];
                ldsm_x4(ak[0], ak[1], ak[2], ak[3], akA); akA += 32;
                ldsm_x4(ar[0], ar[1], ar[2], ar[3], arA); arA += 32;
#pragma unroll
                for (int nf = 0; nf < 4; nf++)
                    mma_tf32(sf[nf], ak, bq[wn * 4 + nf]);
#pragma unroll
                for (int nf = 0; nf < 8; nf++)
                    if (nf >= nf_lo && nf <= nf_hi)
                        mma_tf32(bdf[nf], ar, bq[nf]);
            }
        }
        __syncthreads();               // all uK/uR mma+bd1 reads done

        // spill banded BD^T into sBDT (alias over uR); prefetch K(t+1)
#pragma unroll
        for (int nf = 0; nf < 8; nf++) {
            if (nf >= nf_lo && nf <= nf_hi) {
                int j = sB * 16 + g;
                int q = nf * 8 + 2 * tg;
                *(float2*)&sBDT[j * 68 + q]       = make_float2(bdf[nf].x, bdf[nf].y);
                *(float2*)&sBDT[(j + 8) * 68 + q] = make_float2(bdf[nf].z, bdf[nf].w);
            }
        }
        issueK(k0n); CP_COMMIT();      // groups: [V(t)?, K(t+1)]
        __syncthreads();               // sBDT visible

        // softmax on in-register S^T; store P as [q][key]
        float mk2[2];
#pragma unroll
        for (int half = 0; half < 2; half++) {
            int k = k0 + wm * 16 + g + half * 8;
            mk2[half] = (k >= MM)
                ? fminf(fmaxf(((float)(k - MM) + spanv * (float)QQ) * (1.0f / 33.0f), 0.0f), 1.0f)
                : 1.0f;
        }
        const bool lastT = (t == ntiles - 1);
#pragma unroll
        for (int nf = 0; nf < 4; nf++) {
            float sv[4] = {sf[nf].x, sf[nf].y, sf[nf].z, sf[nf].w};
            uint32_t pt[4];
#pragma unroll
            for (int e = 0; e < 4; e++) {
                int half = e >> 1, p = e & 1;
                int key = wm * 16 + g + half * 8;
                int q = wn * 32 + nf * 8 + 2 * tg + p;
                int j = key + 63 - q;
                float b1 = sB1[2 * j] + sB1[2 * j + 1];
                float val = (sv[e] + sBDT[j * 68 + q] + b1) * (1.0f / 64.0f);
                float ex = __expf(val);
                if (lastT && (k0 + key > MM + q0 + q)) ex = 0.f;
                float em = ex * mk2[half];
                lfp[nf * 2 + p] += ex;
                lmp[nf * 2 + p] += em;
                pt[e] = f2tf(em);
            }
            int q = wn * 32 + nf * 8 + 2 * tg;
            int key = wm * 16 + g;
            uPT[q * 68 + key]           = pt[0];
            uPT[(q + 1) * 68 + key]     = pt[1];
            uPT[q * 68 + key + 8]       = pt[2];
            uPT[(q + 1) * 68 + key + 8] = pt[3];
        }
        CP_WAIT(1);                    // V(t) arrived (oldest of [V(t), K(t+1)])
        __syncthreads();               // uPT + all threads' V visible

        // O^T += V^T * P^T; prefetch Rel(t+1) into uR (dead until next mma)
        issueR(k0n); CP_COMMIT();      // groups: [K(t+1), R(t+1)]
        {
            uint32_t bpA[2] = {bpOff[0], bpOff[1]};
#pragma unroll
            for (int ks = 0; ks < 64; ks += 8) {
                uint32_t av[4];
                int m = wm * 16;
                av[0] = uV[(ks + tg) * 72 + m + g];
                av[1] = uV[(ks + tg) * 72 + m + g + 8];
                av[2] = uV[(ks + tg + 4) * 72 + m + g];
                av[3] = uV[(ks + tg + 4) * 72 + m + g + 8];
                uint32_t bp[4][2];
#pragma unroll
                for (int p = 0; p < 2; p++) {
                    ldsm_x4(bp[2 * p][0], bp[2 * p][1],
                            bp[2 * p + 1][0], bp[2 * p + 1][1], bpA[p]);
                    bpA[p] += 32;
                }
#pragma unroll
                for (int nf = 0; nf < 4; nf++)
                    mma_tf32(o[nf], av, bp[nf]);
            }
        }
    }
    CP_WAIT(0);                        // drain tail prefetches (dead data)

    // reduce lf/lm over g lanes
#pragma unroll
    for (int s = 0; s < 8; s++) {
#pragma unroll
        for (int off = 4; off <= 16; off <<= 1) {
            lfp[s] += __shfl_xor_sync(0xffffffffu, lfp[s], off);
            lmp[s] += __shfl_xor_sync(0xffffffffu, lmp[s], off);
        }
    }
    if (g == 0) {
#pragma unroll
        for (int nf = 0; nf < 4; nf++) {
            int q = wn * 32 + nf * 8 + 2 * tg;
            *(float2*)&sRM[wm * 64 + q] = make_float2(lmp[nf * 2], lmp[nf * 2 + 1]);
            *(float2*)&sRF[wm * 64 + q] = make_float2(lfp[nf * 2], lfp[nf * 2 + 1]);
        }
    }
    __syncthreads();
    if (tid < 64) {
        float lm = sRM[tid] + sRM[64 + tid] + sRM[128 + tid] + sRM[192 + tid];
        float lf = sRF[tid] + sRF[64 + tid] + sRF[128 + tid] + sRF[192 + tid];
        sIv[tid] = 1.0f / (lm + 1e-8f * lf);
    }
    __syncthreads();

    // write output (tf32-rounded — feeds final GEMM's A operand)
#pragma unroll
    for (int nf = 0; nf < 4; nf++) {
        int q = wn * 32 + nf * 8 + 2 * tg;
        int d = wm * 16 + g;
        float i0 = sIv[q], i1 = sIv[q + 1];
        size_t base0 = ((size_t)(b * QQ + q0 + q)) * HID + h * 64;
        size_t base1 = base0 + HID;
        Out[base0 + d]     = f2tff(o[nf].x * i0);
        Out[base1 + d]     = f2tff(o[nf].y * i1);
        Out[base0 + d + 8] = f2tff(o[nf].z * i0);
        Out[base1 + d + 8] = f2tff(o[nf].w * i1);
    }
}

// ---------------- launch -----------------------------------------------------
extern "C" void kernel_launch(void* const* d_in, const int* in_sizes, int n_in,
                              void* d_out, int out_size)
{
    const float* query     = (const float*)d_in[0];
    const float* memory    = (const float*)d_in[1];
    const float* Wq        = (const float*)d_in[2];
    const float* Wk        = (const float*)d_in[3];
    const float* Wv        = (const float*)d_in[4];
    const float* Wo        = (const float*)d_in[5];
    const float* Wr        = (const float*)d_in[6];
    const float* gamma_mem = (const float*)d_in[7];
    const float* beta_mem  = (const float*)d_in[8];
    const float* gamma_q   = (const float*)d_in[9];
    const float* beta_q    = (const float*)d_in[10];
    const float* rwb       = (const float*)d_in[11];
    const float* rrb       = (const float*)d_in[12];
    const float* span      = (const float*)d_in[13];
    float* out = (float*)d_out;

    float *kvln, *qln, *pe, *Qp, *Kp, *Vp, *Rel, *attn, *Wtf;
    cudaGetSymbolAddress((void**)&kvln, g_kvln);
    cudaGetSymbolAddress((void**)&qln,  g_qln);
    cudaGetSymbolAddress((void**)&pe,   g_pe);
    cudaGetSymbolAddress((void**)&Qp,   g_Qp);
    cudaGetSymbolAddress((void**)&Kp,   g_Kp);
    cudaGetSymbolAddress((void**)&Vp,   g_Vp);
    cudaGetSymbolAddress((void**)&Rel,  g_Rel);
    cudaGetSymbolAddress((void**)&attn, g_attn);
    cudaGetSymbolAddress((void**)&Wtf,  g_Wtf);

    float* Wq_t = Wtf + 0 * (size_t)HID * HID;
    float* Wk_t = Wtf + 1 * (size_t)HID * HID;
    float* Wv_t = Wtf + 2 * (size_t)HID * HID;
    float* Wr_t = Wtf + 3 * (size_t)HID * HID;
    float* Wo_t = Wtf + 4 * (size_t)HID * HID;

    cudaFuncSetAttribute(attn_tf32, cudaFuncAttributeMaxDynamicSharedMemorySize,
                         ATTN_SMEM_BYTES);
    cudaFuncSetAttribute(sgemm_tf32, cudaFuncAttributeMaxDynamicSharedMemorySize,
                         GEMM_SMEM_BYTES);

    // Fork/join side stream (created once at first, uncaptured, call).
    static cudaStream_t sSide = nullptr;
    static cudaEvent_t  eFork = nullptr, eJoin = nullptr;
    if (sSide == nullptr) {
        cudaStreamCreateWithFlags(&sSide, cudaStreamNonBlocking);
        cudaEventCreateWithFlags(&eFork, cudaEventDisableTiming);
        cudaEventCreateWithFlags(&eJoin, cudaEventDisableTiming);
    }
    cudaStream_t s0 = 0;

    const int W4 = (HID * HID) / 4 / 256;

    // fork
    cudaEventRecord(eFork, s0);
    cudaStreamWaitEvent(sSide, eFork, 0);

    // branch A (side): ln_q, posemb, Wq/Wr/Wo roundings, Qp-gemm, Rel-gemm
    ln_q_kernel <<<BB * QQ, 256, 0, sSide>>>(query, gamma_q, beta_q, qln);
    posemb_kernel<<<KK, 512, 0, sSide>>>(pe);
    round_tf32_kernel<<<W4, 256, 0, sSide>>>(Wq, Wq_t);
    round_tf32_kernel<<<W4, 256, 0, sSide>>>(Wr, Wr_t);
    round_tf32_kernel<<<W4, 256, 0, sSide>>>(Wo, Wo_t);
    sgemm_tf32<<<dim3(8, (BB * QQ) / 128), 256, GEMM_SMEM_BYTES, sSide>>>(qln, Wq_t, Qp, 1);
    sgemm_tf32<<<dim3(8, KK / 128),        256, GEMM_SMEM_BYTES, sSide>>>(pe,  Wr_t, Rel, 1);
    cudaEventRecord(eJoin, sSide);

    // branch 0 (main): ln_kv, Wk/Wv roundings, Kp-gemm, Vp-gemm
    ln_kv_kernel<<<BB * KK, 256, 0, s0>>>(memory, query, gamma_mem, beta_mem, kvln);
    round_tf32_kernel<<<W4, 256, 0, s0>>>(Wk, Wk_t);
    round_tf32_kernel<<<W4, 256, 0, s0>>>(Wv, Wv_t);
    sgemm_tf32<<<dim3(8, (BB * KK) / 128), 256, GEMM_SMEM_BYTES, s0>>>(kvln, Wk_t, Kp, 1);
    sgemm_tf32<<<dim3(8, (BB * KK) / 128), 256, GEMM_SMEM_BYTES, s0>>>(kvln, Wv_t, Vp, 1);

    // join
    cudaStreamWaitEvent(s0, eJoin, 0);

    attn_tf32<<<dim3(QQ / 64, BB * HH), 256, ATTN_SMEM_BYTES, s0>>>(
        Qp, Kp, Vp, Rel, rwb, rrb, span, attn);

    sgemm_tf32<<<dim3(8, (BB * QQ) / 128), 256, GEMM_SMEM_BYTES, s0>>>(attn, Wo_t, out, 0);
}

// round 16
// speedup vs baseline: 1.6196x; 1.6196x over previous
#include <cuda_runtime.h>
#include <cuda_bf16.h>
#include <math.h>
#include <stdint.h>

// Problem constants
constexpr int BB = 2;
constexpr int QQ = 2048;
constexpr int MM = 2048;
constexpr int HH = 16;
constexpr int HID = 1024;      // H*D
constexpr int KK = MM + QQ;    // 4096

// ---------------- tf32 mma helpers ------------------------------------------
__device__ __forceinline__ uint32_t f2tf(float f)
{
    uint32_t r;
    asm("cvt.rna.tf32.f32 %0, %1;" : "=r"(r) : "f"(f));
    return r;
}
__device__ __forceinline__ float f2tff(float f)
{
    return __uint_as_float(f2tf(f));
}
__device__ __forceinline__ void mma_tf32(float4& c, const uint32_t* a, const uint32_t* b)
{
    asm volatile("mma.sync.aligned.m16n8k8.row.col.f32.tf32.tf32.f32 "
                 "{%0,%1,%2,%3}, {%4,%5,%6,%7}, {%8,%9}, {%0,%1,%2,%3};\n"
                 : "+f"(c.x), "+f"(c.y), "+f"(c.z), "+f"(c.w)
                 : "r"(a[0]), "r"(a[1]), "r"(a[2]), "r"(a[3]),
                   "r"(b[0]), "r"(b[1]));
}
__device__ __forceinline__ void cpa16(void* s, const void* g)   // L1-bypass (streaming)
{
    uint32_t sa = (uint32_t)__cvta_generic_to_shared(s);
    asm volatile("cp.async.cg.shared.global [%0], [%1], 16;\n" :: "r"(sa), "l"(g));
}
__device__ __forceinline__ void cpa16ca(void* s, const void* g) // L1-allocating
{
    uint32_t sa = (uint32_t)__cvta_generic_to_shared(s);
    asm volatile("cp.async.ca.shared.global [%0], [%1], 16;\n" :: "r"(sa), "l"(g));
}
__device__ __forceinline__ void cpa16ca_z(void* s, const void* g, int nbytes)
{
    uint32_t sa = (uint32_t)__cvta_generic_to_shared(s);
    asm volatile("cp.async.ca.shared.global [%0], [%1], 16, %2;\n"
                 :: "r"(sa), "l"(g), "r"(nbytes));
}
#define CP_COMMIT()  asm volatile("cp.async.commit_group;\n" ::: "memory")
#define CP_WAIT(N)   asm volatile("cp.async.wait_group %0;\n" :: "n"(N) : "memory")
__device__ __forceinline__ float ex2_approx(float x)
{
    float r;
    asm("ex2.approx.f32 %0, %1;" : "=f"(r) : "f"(x));
    return r;
}

// ---------------- scratch (device globals; no allocations allowed) ----------
__device__ float g_kvln[(size_t)BB * KK * HID];
__device__ float g_qln [(size_t)BB * QQ * HID];
__device__ float g_pe  [(size_t)KK * HID];
__device__ float g_Qp  [(size_t)BB * QQ * HID];
__device__ float g_Kp  [(size_t)BB * KK * HID];
__device__ float g_Vp  [(size_t)BB * KK * HID];
__device__ float g_Rel [(size_t)KK * HID];
__device__ float g_attn[(size_t)BB * QQ * HID];
__device__ float g_Wtf [(size_t)5 * HID * HID];   // tf32-rounded weight copies

// ---------------- tf32 rounding prepass (weights) ----------------------------
__global__ __launch_bounds__(256)
void round_tf32_kernel(const float* __restrict__ src, float* __restrict__ dst)
{
    int i = blockIdx.x * 256 + threadIdx.x;      // float4 index
    float4 v = ((const float4*)src)[i];
    ((float4*)dst)[i] = make_float4(f2tff(v.x), f2tff(v.y), f2tff(v.z), f2tff(v.w));
}

// ---------------- LayerNorm over rows of length 1024 (tf32-rounded out) -----
__device__ __forceinline__ void ln_row_1024(const float* __restrict__ src,
                                            float* __restrict__ dst,
                                            const float* __restrict__ gamma,
                                            const float* __restrict__ beta)
{
    __shared__ float red[16];
    int tid = threadIdx.x;                    // 256 threads, 4 floats each
    float4 v = ((const float4*)src)[tid];
    float s1 = v.x + v.y + v.z + v.w;
    float s2 = v.x*v.x + v.y*v.y + v.z*v.z + v.w*v.w;
#pragma unroll
    for (int off = 16; off; off >>= 1) {
        s1 += __shfl_xor_sync(0xffffffffu, s1, off);
        s2 += __shfl_xor_sync(0xffffffffu, s2, off);
    }
    if ((tid & 31) == 0) { red[tid >> 5] = s1; red[8 + (tid >> 5)] = s2; }
    __syncthreads();
    if (tid == 0) {
        float a = 0.f, b = 0.f;
#pragma unroll
        for (int i = 0; i < 8; i++) { a += red[i]; b += red[8 + i]; }
        float mu  = a * (1.0f / 1024.0f);
        float var = b * (1.0f / 1024.0f) - mu * mu;
        red[0] = mu;
        red[1] = rsqrtf(var + 1e-3f);
    }
    __syncthreads();
    float mu = red[0], sc = red[1];
    float4 g  = ((const float4*)gamma)[tid];
    float4 bb = ((const float4*)beta)[tid];
    float4 o;
    o.x = f2tff((v.x - mu) * sc * g.x + bb.x);
    o.y = f2tff((v.y - mu) * sc * g.y + bb.y);
    o.z = f2tff((v.z - mu) * sc * g.z + bb.z);
    o.w = f2tff((v.w - mu) * sc * g.w + bb.w);
    ((float4*)dst)[tid] = o;
}

__global__ __launch_bounds__(256)
void ln_kv_kernel(const float* __restrict__ mem, const float* __restrict__ qry,
                  const float* __restrict__ gamma, const float* __restrict__ beta,
                  float* __restrict__ out)
{
    int row = blockIdx.x;
    int b = row / KK, r = row % KK;
    const float* src = (r < MM) ? (mem + ((size_t)b * MM + r) * HID)
                                : (qry + ((size_t)b * QQ + (r - MM)) * HID);
    ln_row_1024(src, out + (size_t)row * HID, gamma, beta);
}

__global__ __launch_bounds__(256)
void ln_q_kernel(const float* __restrict__ qry,
                 const float* __restrict__ gamma, const float* __restrict__ beta,
                 float* __restrict__ out)
{
    int row = blockIdx.x;
    ln_row_1024(qry + (size_t)row * HID, out + (size_t)row * HID, gamma, beta);
}

// ---------------- sinusoidal relative position embedding (fast MUFU) --------
__global__ __launch_bounds__(512)
void posemb_kernel(float* __restrict__ pe)
{
    int j = blockIdx.x;                        // 0 .. KK-1
    int i = threadIdx.x;                       // 0 .. 511
    float pos = (float)(KK - 1 - j);
    const float c2 = -13.287712379549449f / 512.0f;
    float invf = ex2_approx(c2 * (float)i);
    float ang  = pos * invf;
    float k = rintf(ang * 0.15915494309189535f);
    float a = fmaf(k, -6.2831854820251465f, ang);
    a = fmaf(k, 1.7484555e-7f, a);
    float s, cc;
    __sincosf(a, &s, &cc);
    pe[(size_t)j * HID + i]       = f2tff(s);
    pe[(size_t)j * HID + 512 + i] = f2tff(cc);
}

// ---------------- tf32 SGEMM: C[M,1024] = A[M,1024]*B[1024,1024] ------------
// Inputs pre-rounded to tf32 (stored as fp32); no cvt in inner loop.
constexpr int GA_STRIDE = 20;
constexpr int GB_STRIDE = 136;
constexpr int GA_BUF = 128 * GA_STRIDE;   // 2560
constexpr int GB_BUF = 16 * GB_STRIDE;    // 2176
constexpr int GEMM_SMEM_BYTES = 3 * (GA_BUF + GB_BUF) * 4;   // 56,832 B

__global__ __launch_bounds__(256, 2)
void sgemm_tf32(const float* __restrict__ A, const float* __restrict__ B,
                float* __restrict__ C, int roundC)
{
    extern __shared__ float gsm[];
    float* sA = gsm;                  // 3 x [128][20]
    float* sB = gsm + 3 * GA_BUF;     // 3 x [16][136]
    const int tid = threadIdx.x;
    const int lane = tid & 31, wid = tid >> 5;
    const int g = lane >> 2, tg = lane & 3;
    const int wm = (wid & 1) * 64, wn = (wid >> 1) * 32;
    const int row0 = blockIdx.y * 128, col0 = blockIdx.x * 128;

    const int af4a = tid,        af4b = tid + 256;
    const int ar_a = af4a >> 2,  ac_a = (af4a & 3) << 2;
    const int ar_b = af4b >> 2,  ac_b = (af4b & 3) << 2;
    const int br_a = af4a >> 5,  bc_a = (af4a & 31) << 2;
    const int br_b = af4b >> 5,  bc_b = (af4b & 31) << 2;

    auto issue = [&](int buf, int k0) {
        float* a = sA + buf * GA_BUF;
        float* bfp = sB + buf * GB_BUF;
        cpa16(&a[ar_a * GA_STRIDE + ac_a], &A[(size_t)(row0 + ar_a) * 1024 + k0 + ac_a]);
        cpa16(&a[ar_b * GA_STRIDE + ac_b], &A[(size_t)(row0 + ar_b) * 1024 + k0 + ac_b]);
        cpa16(&bfp[br_a * GB_STRIDE + bc_a], &B[(size_t)(k0 + br_a) * 1024 + col0 + bc_a]);
        cpa16(&bfp[br_b * GB_STRIDE + bc_b], &B[(size_t)(k0 + br_b) * 1024 + col0 + bc_b]);
    };

    issue(0, 0);
    CP_COMMIT();
    issue(1, 16);
    CP_COMMIT();

    float4 acc[4][4];
#pragma unroll
    for (int i = 0; i < 4; i++)
#pragma unroll
        for (int j = 0; j < 4; j++) acc[i][j] = make_float4(0.f, 0.f, 0.f, 0.f);

    for (int it = 0; it < 64; it++) {
        CP_WAIT(1);
        __syncthreads();
        if (it + 2 < 64) issue((it + 2) % 3, (it + 2) * 16);
        CP_COMMIT();

        const float* a = sA + (it % 3) * GA_BUF;
        const float* bs = sB + (it % 3) * GB_BUF;
#pragma unroll
        for (int kk = 0; kk < 16; kk += 8) {
            uint32_t af[4][4], bf[4][2];
#pragma unroll
            for (int mf = 0; mf < 4; mf++) {
                int m = wm + mf * 16;
                af[mf][0] = __float_as_uint(a[(m + g) * GA_STRIDE + kk + tg]);
                af[mf][1] = __float_as_uint(a[(m + g + 8) * GA_STRIDE + kk + tg]);
                af[mf][2] = __float_as_uint(a[(m + g) * GA_STRIDE + kk + tg + 4]);
                af[mf][3] = __float_as_uint(a[(m + g + 8) * GA_STRIDE + kk + tg + 4]);
            }
#pragma unroll
            for (int nf = 0; nf < 4; nf++) {
                int n = wn + nf * 8;
                bf[nf][0] = __float_as_uint(bs[(kk + tg) * GB_STRIDE + n + g]);
                bf[nf][1] = __float_as_uint(bs[(kk + tg + 4) * GB_STRIDE + n + g]);
            }
#pragma unroll
            for (int mf = 0; mf < 4; mf++)
#pragma unroll
                for (int nf = 0; nf < 4; nf++)
                    mma_tf32(acc[mf][nf], af[mf], bf[nf]);
        }
    }
    if (roundC) {
#pragma unroll
        for (int mf = 0; mf < 4; mf++)
#pragma unroll
            for (int nf = 0; nf < 4; nf++) {
                int r = row0 + wm + mf * 16 + g;
                int c = col0 + wn + nf * 8 + 2 * tg;
                *(float2*)&C[(size_t)r * 1024 + c] =
                    make_float2(f2tff(acc[mf][nf].x), f2tff(acc[mf][nf].y));
                *(float2*)&C[(size_t)(r + 8) * 1024 + c] =
                    make_float2(f2tff(acc[mf][nf].z), f2tff(acc[mf][nf].w));
            }
    } else {
#pragma unroll
        for (int mf = 0; mf < 4; mf++)
#pragma unroll
            for (int nf = 0; nf < 4; nf++) {
                int r = row0 + wm + mf * 16 + g;
                int c = col0 + wn + nf * 8 + 2 * tg;
                *(float2*)&C[(size_t)r * 1024 + c] = make_float2(acc[mf][nf].x, acc[mf][nf].y);
                *(float2*)&C[(size_t)(r + 8) * 1024 + c] = make_float2(acc[mf][nf].z, acc[mf][nf].w);
            }
    }
}

// ---------------- fused relative attention (tf32 mma, banded BD, async) -----
// grid: (Q/64, B*H); 256 threads, 8 warps.  (round-14 structure, LDS frags)
constexpr int AT_SQ  = 0;       // Qw^T [64 d][72]  tf32
constexpr int AT_SK  = 4608;    // K    [64 k][68]  tf32 (pre-rounded fp32)
constexpr int AT_SV  = 8960;    // V    [64 k][72]  tf32
constexpr int AT_SR  = 13568;   // Rel  [128 j][68] tf32 / BD^T f32 (alias)
constexpr int AT_SPT = 22272;   // P^T  [64 k][72]  tf32
constexpr int AT_SB1 = 26880;   // bd1 [128] f32
constexpr int AT_SDL = 27136;   // dl   [64]  f32
constexpr int AT_SRM = 27200;   // lm red [4][64]
constexpr int AT_SRF = 27456;   // lf red [4][64]
constexpr int AT_SIV = 27712;   // inv  [64]
constexpr int AT_TOT = 27776;
constexpr int ATTN_SMEM_BYTES = AT_TOT * 4;     // 111,104 B -> 2 CTAs/SM

__global__ __launch_bounds__(256, 2)
void attn_tf32(const float* __restrict__ Qp, const float* __restrict__ Kp,
               const float* __restrict__ Vp, const float* __restrict__ Rel,
               const float* __restrict__ rwb, const float* __restrict__ rrb,
               const float* __restrict__ span, float* __restrict__ Out)
{
    extern __shared__ float sm[];
    uint32_t* uQ  = (uint32_t*)(sm + AT_SQ);
    uint32_t* uK  = (uint32_t*)(sm + AT_SK);
    uint32_t* uV  = (uint32_t*)(sm + AT_SV);
    uint32_t* uR  = (uint32_t*)(sm + AT_SR);
    float*   sBDT = sm + AT_SR;                  // alias over Rel
    uint32_t* uPT = (uint32_t*)(sm + AT_SPT);
    float* sB1 = sm + AT_SB1;
    float* sDl = sm + AT_SDL;
    float* sRM = sm + AT_SRM;
    float* sRF = sm + AT_SRF;
    float* sIv = sm + AT_SIV;

    const int tid = threadIdx.x;
    const int lane = tid & 31, wid = tid >> 5;
    const int g = lane >> 2, tg = lane & 3;
    const int wm = wid & 3;            // key/d strip (x16) for AD / PV
    const int wn = wid >> 2;           // q half (x32)
    // BD band assignment: strip sB = 7-wid aligns bd q-range with sf q-range
    const int sB  = 7 - wid;
    const int nf_lo = max(0, 6 - 2 * sB);
    const int nf_hi = min(7, 15 - 2 * sB);
    const int lo2 = min(nf_lo, wn * 4);
    const int hi2 = max(nf_hi, wn * 4 + 3);
    // big-work CTAs launch first
    const int qt = (int)gridDim.x - 1 - (int)blockIdx.x;
    const int q0 = qt * 64;
    const int b = blockIdx.y >> 4, h = blockIdx.y & 15;
    const float spanv = span[h];

    // staging issuers (cp.async.ca — L1-allocating; all operands pre-rounded)
    auto issueK = [&](int k0s) {
#pragma unroll
        for (int idx = tid; idx < 1024; idx += 256) {
            int kk = idx >> 4, d4 = (idx & 15) << 2;
            cpa16ca(&uK[kk * 68 + d4],
                    &Kp[((size_t)(b * KK + k0s + kk)) * HID + h * 64 + d4]);
        }
    };
    auto issueV = [&](int k0s) {
#pragma unroll
        for (int idx = tid; idx < 1024; idx += 256) {
            int kk = idx >> 4, d4 = (idx & 15) << 2;
            cpa16ca(&uV[kk * 72 + d4],
                    &Vp[((size_t)(b * KK + k0s + kk)) * HID + h * 64 + d4]);
        }
    };
    auto issueR = [&](int k0s) {
        int jb = k0s + (QQ - 1) - (q0 + 63);
#pragma unroll
        for (int idx = tid; idx < 2048; idx += 256) {
            int jj = idx >> 4, d4 = (idx & 15) << 2;
            int j = jb + jj;
            bool ok = (j < KK);
            cpa16ca_z(&uR[jj * 68 + d4],
                      ok ? &Rel[(size_t)j * HID + h * 64 + d4] : (const float*)Rel,
                      ok ? 16 : 0);
        }
    };

    if (tid < 64) sDl[tid] = rrb[h * 64 + tid] - rwb[h * 64 + tid];

    // prologue: K(0), R(0) in flight
    issueK(0); CP_COMMIT();
    issueR(0); CP_COMMIT();

    // stage Qw^T = (q + r_w_bias)^T, tf32 (once per CTA)
    for (int idx = tid; idx < 1024; idx += 256) {
        int qq = idx >> 4, d4 = (idx & 15) << 2;
        float4 qv = *(const float4*)&Qp[((size_t)(b * QQ + q0 + qq)) * HID + h * 64 + d4];
        float4 wb = *(const float4*)&rwb[h * 64 + d4];
        uQ[(d4 + 0) * 72 + qq] = f2tf(qv.x + wb.x);
        uQ[(d4 + 1) * 72 + qq] = f2tf(qv.y + wb.y);
        uQ[(d4 + 2) * 72 + qq] = f2tf(qv.z + wb.z);
        uQ[(d4 + 3) * 72 + qq] = f2tf(qv.w + wb.w);
    }

    float4 o[4];
#pragma unroll
    for (int i = 0; i < 4; i++) o[i] = make_float4(0.f, 0.f, 0.f, 0.f);
    float lfp[8], lmp[8];
#pragma unroll
    for (int i = 0; i < 8; i++) { lfp[i] = 0.f; lmp[i] = 0.f; }

    const int ntiles = 33 + qt;
    for (int t = 0; t < ntiles; t++) {
        const int k0 = t * 64;
        const int k0n = min(k0 + 64, KK - 64);  // clamped prefetch target

        __syncthreads();               // PV(t-1) complete; uV free (Q stage at t=0)
        issueV(k0); CP_COMMIT();       // groups: [K(t), R(t), V(t)]
        CP_WAIT(1);                    // K(t), R(t) arrived (this thread)
        __syncthreads();               // ... visible to all threads

        // bd1[j] = sum_d Rel[j][d] * dl[d]  (128 threads, full dot)
        if (tid < 128) {
            const float* rr = (const float*)&uR[tid * 68];
            float s = 0.f;
#pragma unroll
            for (int d4 = 0; d4 < 64; d4 += 4) {
                float4 r4 = *(const float4*)&rr[d4];
                float4 dl4 = *(const float4*)&sDl[d4];
                s += r4.x * dl4.x + r4.y * dl4.y + r4.z * dl4.z + r4.w * dl4.w;
            }
            sB1[tid] = s;
        }

        // AD^T + banded BD^T mma (shared B-operand = Qw^T)
        float4 sf[4];
        float4 bdf[8];
#pragma unroll
        for (int i = 0; i < 4; i++) sf[i] = make_float4(0.f, 0.f, 0.f, 0.f);
#pragma unroll
        for (int i = 0; i < 8; i++) bdf[i] = make_float4(0.f, 0.f, 0.f, 0.f);
#pragma unroll
        for (int ks = 0; ks < 64; ks += 8) {
            uint32_t bq[8][2];
#pragma unroll
            for (int nf = 0; nf < 8; nf++) {
                if (nf >= lo2 && nf <= hi2) {
                    int n = nf * 8 + g;
                    bq[nf][0] = uQ[(ks + tg) * 72 + n];
                    bq[nf][1] = uQ[(ks + tg + 4) * 72 + n];
                }
            }
            uint32_t ak[4], ar[4];
            {
                int m = wm * 16;
                ak[0] = uK[(m + g) * 68 + ks + tg];
                ak[1] = uK[(m + g + 8) * 68 + ks + tg];
                ak[2] = uK[(m + g) * 68 + ks + tg + 4];
                ak[3] = uK[(m + g + 8) * 68 + ks + tg + 4];
            }
            {
                int m = sB * 16;
                ar[0] = uR[(m + g) * 68 + ks + tg];
                ar[1] = uR[(m + g + 8) * 68 + ks + tg];
                ar[2] = uR[(m + g) * 68 + ks + tg + 4];
                ar[3] = uR[(m + g + 8) * 68 + ks + tg + 4];
            }
#pragma unroll
            for (int nf = 0; nf < 4; nf++)
                mma_tf32(sf[nf], ak, bq[wn * 4 + nf]);
#pragma unroll
            for (int nf = 0; nf < 8; nf++)
                if (nf >= nf_lo && nf <= nf_hi)
                    mma_tf32(bdf[nf], ar, bq[nf]);
        }
        __syncthreads();               // all uK/uR mma+bd1 reads done

        // spill banded BD^T into sBDT (alias over uR); prefetch K(t+1)
#pragma unroll
        for (int nf = 0; nf < 8; nf++) {
            if (nf >= nf_lo && nf <= nf_hi) {
                int j = sB * 16 + g;
                int q = nf * 8 + 2 * tg;
                *(float2*)&sBDT[j * 68 + q]       = make_float2(bdf[nf].x, bdf[nf].y);
                *(float2*)&sBDT[(j + 8) * 68 + q] = make_float2(bdf[nf].z, bdf[nf].w);
            }
        }
        issueK(k0n); CP_COMMIT();      // groups: [V(t)?, K(t+1)]
        __syncthreads();               // sBDT visible

        // softmax on in-register S^T (exp2 with folded log2e/64 scale)
        const float ESC = 0.022542120622634243f;  // log2(e) / 64
        float mk2[2];
#pragma unroll
        for (int half = 0; half < 2; half++) {
            int k = k0 + wm * 16 + g + half * 8;
            mk2[half] = (k >= MM)
                ? fminf(fmaxf(((float)(k - MM) + spanv * (float)QQ) * (1.0f / 33.0f), 0.0f), 1.0f)
                : 1.0f;
        }
        const bool lastT = (t == ntiles - 1);
#pragma unroll
        for (int nf = 0; nf < 4; nf++) {
            float sv[4] = {sf[nf].x, sf[nf].y, sf[nf].z, sf[nf].w};
            uint32_t pt[4];
#pragma unroll
            for (int e = 0; e < 4; e++) {
                int half = e >> 1, p = e & 1;
                int key = wm * 16 + g + half * 8;
                int q = wn * 32 + nf * 8 + 2 * tg + p;
                int j = key + 63 - q;
                float val = (sv[e] + sBDT[j * 68 + q] + sB1[j]) * ESC;
                float ex = ex2_approx(val);
                if (lastT && (k0 + key > MM + q0 + q)) ex = 0.f;
                float em = ex * mk2[half];
                lfp[nf * 2 + p] += ex;
                lmp[nf * 2 + p] += em;
                pt[e] = f2tf(em);
            }
            int q = wn * 32 + nf * 8 + 2 * tg;
            int key = wm * 16 + g;
            *(uint2*)&uPT[key * 72 + q]       = make_uint2(pt[0], pt[1]);
            *(uint2*)&uPT[(key + 8) * 72 + q] = make_uint2(pt[2], pt[3]);
        }
        CP_WAIT(1);                    // V(t) arrived (oldest of [V(t), K(t+1)])
        __syncthreads();               // uPT + all threads' V visible

        // O^T += V^T * P^T; prefetch Rel(t+1) into uR (dead until next mma)
        issueR(k0n); CP_COMMIT();      // groups: [K(t+1), R(t+1)]
#pragma unroll
        for (int ks = 0; ks < 64; ks += 8) {
            uint32_t av[4];
            int m = wm * 16;
            av[0] = uV[(ks + tg) * 72 + m + g];
            av[1] = uV[(ks + tg) * 72 + m + g + 8];
            av[2] = uV[(ks + tg + 4) * 72 + m + g];
            av[3] = uV[(ks + tg + 4) * 72 + m + g + 8];
            uint32_t bp[4][2];
#pragma unroll
            for (int nf = 0; nf < 4; nf++) {
                int n = wn * 32 + nf * 8 + g;
                bp[nf][0] = uPT[(ks + tg) * 72 + n];
                bp[nf][1] = uPT[(ks + tg + 4) * 72 + n];
            }
#pragma unroll
            for (int nf = 0; nf < 4; nf++)
                mma_tf32(o[nf], av, bp[nf]);
        }
    }
    CP_WAIT(0);                        // drain tail prefetches (dead data)

    // reduce lf/lm over g lanes
#pragma unroll
    for (int s = 0; s < 8; s++) {
#pragma unroll
        for (int off = 4; off <= 16; off <<= 1) {
            lfp[s] += __shfl_xor_sync(0xffffffffu, lfp[s], off);
            lmp[s] += __shfl_xor_sync(0xffffffffu, lmp[s], off);
        }
    }
    if (g == 0) {
#pragma unroll
        for (int nf = 0; nf < 4; nf++) {
            int q = wn * 32 + nf * 8 + 2 * tg;
            *(float2*)&sRM[wm * 64 + q] = make_float2(lmp[nf * 2], lmp[nf * 2 + 1]);
            *(float2*)&sRF[wm * 64 + q] = make_float2(lfp[nf * 2], lfp[nf * 2 + 1]);
        }
    }
    __syncthreads();
    if (tid < 64) {
        float lm = sRM[tid] + sRM[64 + tid] + sRM[128 + tid] + sRM[192 + tid];
        float lf = sRF[tid] + sRF[64 + tid] + sRF[128 + tid] + sRF[192 + tid];
        sIv[tid] = 1.0f / (lm + 1e-8f * lf);
    }
    __syncthreads();

    // write output (tf32-rounded — feeds final GEMM's A operand)
#pragma unroll
    for (int nf = 0; nf < 4; nf++) {
        int q = wn * 32 + nf * 8 + 2 * tg;
        int d = wm * 16 + g;
        float i0 = sIv[q], i1 = sIv[q + 1];
        size_t base0 = ((size_t)(b * QQ + q0 + q)) * HID + h * 64;
        size_t base1 = base0 + HID;
        Out[base0 + d]     = f2tff(o[nf].x * i0);
        Out[base1 + d]     = f2tff(o[nf].y * i1);
        Out[base0 + d + 8] = f2tff(o[nf].z * i0);
        Out[base1 + d + 8] = f2tff(o[nf].w * i1);
    }
}

// ---------------- launch -----------------------------------------------------
extern "C" void kernel_launch(void* const* d_in, const int* in_sizes, int n_in,
                              void* d_out, int out_size)
{
    const float* query     = (const float*)d_in[0];
    const float* memory    = (const float*)d_in[1];
    const float* Wq        = (const float*)d_in[2];
    const float* Wk        = (const float*)d_in[3];
    const float* Wv        = (const float*)d_in[4];
    const float* Wo        = (const float*)d_in[5];
    const float* Wr        = (const float*)d_in[6];
    const float* gamma_mem = (const float*)d_in[7];
    const float* beta_mem  = (const float*)d_in[8];
    const float* gamma_q   = (const float*)d_in[9];
    const float* beta_q    = (const float*)d_in[10];
    const float* rwb       = (const float*)d_in[11];
    const float* rrb       = (const float*)d_in[12];
    const float* span      = (const float*)d_in[13];
    float* out = (float*)d_out;

    float *kvln, *qln, *pe, *Qp, *Kp, *Vp, *Rel, *attn, *Wtf;
    cudaGetSymbolAddress((void**)&kvln, g_kvln);
    cudaGetSymbolAddress((void**)&qln,  g_qln);
    cudaGetSymbolAddress((void**)&pe,   g_pe);
    cudaGetSymbolAddress((void**)&Qp,   g_Qp);
    cudaGetSymbolAddress((void**)&Kp,   g_Kp);
    cudaGetSymbolAddress((void**)&Vp,   g_Vp);
    cudaGetSymbolAddress((void**)&Rel,  g_Rel);
    cudaGetSymbolAddress((void**)&attn, g_attn);
    cudaGetSymbolAddress((void**)&Wtf,  g_Wtf);

    float* Wq_t = Wtf + 0 * (size_t)HID * HID;
    float* Wk_t = Wtf + 1 * (size_t)HID * HID;
    float* Wv_t = Wtf + 2 * (size_t)HID * HID;
    float* Wr_t = Wtf + 3 * (size_t)HID * HID;
    float* Wo_t = Wtf + 4 * (size_t)HID * HID;

    cudaFuncSetAttribute(attn_tf32, cudaFuncAttributeMaxDynamicSharedMemorySize,
                         ATTN_SMEM_BYTES);
    cudaFuncSetAttribute(sgemm_tf32, cudaFuncAttributeMaxDynamicSharedMemorySize,
                         GEMM_SMEM_BYTES);

    // Fork/join side stream (created once at first, uncaptured, call).
    static cudaStream_t sSide = nullptr;
    static cudaEvent_t  eFork = nullptr, eJoin = nullptr;
    if (sSide == nullptr) {
        cudaStreamCreateWithFlags(&sSide, cudaStreamNonBlocking);
        cudaEventCreateWithFlags(&eFork, cudaEventDisableTiming);
        cudaEventCreateWithFlags(&eJoin, cudaEventDisableTiming);
    }
    cudaStream_t s0 = 0;

    const int W4 = (HID * HID) / 4 / 256;

    // fork
    cudaEventRecord(eFork, s0);
    cudaStreamWaitEvent(sSide, eFork, 0);

    // branch A (side): ln_q, posemb, Wq/Wr/Wo roundings, Qp-gemm, Rel-gemm
    ln_q_kernel <<<BB * QQ, 256, 0, sSide>>>(query, gamma_q, beta_q, qln);
    posemb_kernel<<<KK, 512, 0, sSide>>>(pe);
    round_tf32_kernel<<<W4, 256, 0, sSide>>>(Wq, Wq_t);
    round_tf32_kernel<<<W4, 256, 0, sSide>>>(Wr, Wr_t);
    round_tf32_kernel<<<W4, 256, 0, sSide>>>(Wo, Wo_t);
    sgemm_tf32<<<dim3(8, (BB * QQ) / 128), 256, GEMM_SMEM_BYTES, sSide>>>(qln, Wq_t, Qp, 1);
    sgemm_tf32<<<dim3(8, KK / 128),        256, GEMM_SMEM_BYTES, sSide>>>(pe,  Wr_t, Rel, 1);
    cudaEventRecord(eJoin, sSide);

    // branch 0 (main): ln_kv, Wk/Wv roundings, Kp-gemm, Vp-gemm
    ln_kv_kernel<<<BB * KK, 256, 0, s0>>>(memory, query, gamma_mem, beta_mem, kvln);
    round_tf32_kernel<<<W4, 256, 0, s0>>>(Wk, Wk_t);
    round_tf32_kernel<<<W4, 256, 0, s0>>>(Wv, Wv_t);
    sgemm_tf32<<<dim3(8, (BB * KK) / 128), 256, GEMM_SMEM_BYTES, s0>>>(kvln, Wk_t, Kp, 1);
    sgemm_tf32<<<dim3(8, (BB * KK) / 128), 256, GEMM_SMEM_BYTES, s0>>>(kvln, Wv_t, Vp, 1);

    // join
    cudaStreamWaitEvent(s0, eJoin, 0);

    attn_tf32<<<dim3(QQ / 64, BB * HH), 256, ATTN_SMEM_BYTES, s0>>>(
        Qp, Kp, Vp, Rel, rwb, rrb, span, attn);

    sgemm_tf32<<<dim3(8, (BB * QQ) / 128), 256, GEMM_SMEM_BYTES, s0>>>(attn, Wo_t, out, 0);
}

// round 17
// speedup vs baseline: 1.6489x; 1.0181x over previous
#include <cuda_runtime.h>
#include <cuda_bf16.h>
#include <math.h>
#include <stdint.h>

// Problem constants
constexpr int BB = 2;
constexpr int QQ = 2048;
constexpr int MM = 2048;
constexpr int HH = 16;
constexpr int HID = 1024;      // H*D
constexpr int KK = MM + QQ;    // 4096

// ---------------- tf32 mma helpers ------------------------------------------
__device__ __forceinline__ uint32_t f2tf(float f)
{
    uint32_t r;
    asm("cvt.rna.tf32.f32 %0, %1;" : "=r"(r) : "f"(f));
    return r;
}
__device__ __forceinline__ float f2tff(float f)
{
    return __uint_as_float(f2tf(f));
}
__device__ __forceinline__ void mma_tf32(float4& c, const uint32_t* a, const uint32_t* b)
{
    asm volatile("mma.sync.aligned.m16n8k8.row.col.f32.tf32.tf32.f32 "
                 "{%0,%1,%2,%3}, {%4,%5,%6,%7}, {%8,%9}, {%0,%1,%2,%3};\n"
                 : "+f"(c.x), "+f"(c.y), "+f"(c.z), "+f"(c.w)
                 : "r"(a[0]), "r"(a[1]), "r"(a[2]), "r"(a[3]),
                   "r"(b[0]), "r"(b[1]));
}
__device__ __forceinline__ void cpa16(void* s, const void* g)   // L1-bypass (streaming)
{
    uint32_t sa = (uint32_t)__cvta_generic_to_shared(s);
    asm volatile("cp.async.cg.shared.global [%0], [%1], 16;\n" :: "r"(sa), "l"(g));
}
__device__ __forceinline__ void cpa16ca(void* s, const void* g) // L1-allocating
{
    uint32_t sa = (uint32_t)__cvta_generic_to_shared(s);
    asm volatile("cp.async.ca.shared.global [%0], [%1], 16;\n" :: "r"(sa), "l"(g));
}
__device__ __forceinline__ void cpa16ca_z(void* s, const void* g, int nbytes)
{
    uint32_t sa = (uint32_t)__cvta_generic_to_shared(s);
    asm volatile("cp.async.ca.shared.global [%0], [%1], 16, %2;\n"
                 :: "r"(sa), "l"(g), "r"(nbytes));
}
#define CP_COMMIT()  asm volatile("cp.async.commit_group;\n" ::: "memory")
#define CP_WAIT(N)   asm volatile("cp.async.wait_group %0;\n" :: "n"(N) : "memory")
__device__ __forceinline__ float ex2_approx(float x)
{
    float r;
    asm("ex2.approx.f32 %0, %1;" : "=f"(r) : "f"(x));
    return r;
}

// ---------------- scratch (device globals; no allocations allowed) ----------
__device__ float g_kvln[(size_t)BB * KK * HID];
__device__ float g_qln [(size_t)BB * QQ * HID];
__device__ float g_pe  [(size_t)KK * HID];
__device__ float g_Qp  [(size_t)BB * QQ * HID];
__device__ float g_Kp  [(size_t)BB * KK * HID];
__device__ float g_Vp  [(size_t)BB * KK * HID];
__device__ float g_Rel [(size_t)KK * HID];
__device__ float g_attn[(size_t)BB * QQ * HID];
__device__ float g_Wtf [(size_t)5 * HID * HID];   // tf32-rounded weight copies

// ---------------- tf32 rounding prepass (weights) ----------------------------
__global__ __launch_bounds__(256)
void round_tf32_kernel(const float* __restrict__ src, float* __restrict__ dst)
{
    int i = blockIdx.x * 256 + threadIdx.x;      // float4 index
    float4 v = ((const float4*)src)[i];
    ((float4*)dst)[i] = make_float4(f2tff(v.x), f2tff(v.y), f2tff(v.z), f2tff(v.w));
}

// ---------------- LayerNorm over rows of length 1024 (tf32-rounded out) -----
__device__ __forceinline__ void ln_row_1024(const float* __restrict__ src,
                                            float* __restrict__ dst,
                                            const float* __restrict__ gamma,
                                            const float* __restrict__ beta)
{
    __shared__ float red[16];
    int tid = threadIdx.x;                    // 256 threads, 4 floats each
    float4 v = ((const float4*)src)[tid];
    float s1 = v.x + v.y + v.z + v.w;
    float s2 = v.x*v.x + v.y*v.y + v.z*v.z + v.w*v.w;
#pragma unroll
    for (int off = 16; off; off >>= 1) {
        s1 += __shfl_xor_sync(0xffffffffu, s1, off);
        s2 += __shfl_xor_sync(0xffffffffu, s2, off);
    }
    if ((tid & 31) == 0) { red[tid >> 5] = s1; red[8 + (tid >> 5)] = s2; }
    __syncthreads();
    if (tid == 0) {
        float a = 0.f, b = 0.f;
#pragma unroll
        for (int i = 0; i < 8; i++) { a += red[i]; b += red[8 + i]; }
        float mu  = a * (1.0f / 1024.0f);
        float var = b * (1.0f / 1024.0f) - mu * mu;
        red[0] = mu;
        red[1] = rsqrtf(var + 1e-3f);
    }
    __syncthreads();
    float mu = red[0], sc = red[1];
    float4 g  = ((const float4*)gamma)[tid];
    float4 bb = ((const float4*)beta)[tid];
    float4 o;
    o.x = f2tff((v.x - mu) * sc * g.x + bb.x);
    o.y = f2tff((v.y - mu) * sc * g.y + bb.y);
    o.z = f2tff((v.z - mu) * sc * g.z + bb.z);
    o.w = f2tff((v.w - mu) * sc * g.w + bb.w);
    ((float4*)dst)[tid] = o;
}

__global__ __launch_bounds__(256)
void ln_kv_kernel(const float* __restrict__ mem, const float* __restrict__ qry,
                  const float* __restrict__ gamma, const float* __restrict__ beta,
                  float* __restrict__ out)
{
    int row = blockIdx.x;
    int b = row / KK, r = row % KK;
    const float* src = (r < MM) ? (mem + ((size_t)b * MM + r) * HID)
                                : (qry + ((size_t)b * QQ + (r - MM)) * HID);
    ln_row_1024(src, out + (size_t)row * HID, gamma, beta);
}

__global__ __launch_bounds__(256)
void ln_q_kernel(const float* __restrict__ qry,
                 const float* __restrict__ gamma, const float* __restrict__ beta,
                 float* __restrict__ out)
{
    int row = blockIdx.x;
    ln_row_1024(qry + (size_t)row * HID, out + (size_t)row * HID, gamma, beta);
}

// ---------------- sinusoidal relative position embedding (fast MUFU) --------
__global__ __launch_bounds__(512)
void posemb_kernel(float* __restrict__ pe)
{
    int j = blockIdx.x;                        // 0 .. KK-1
    int i = threadIdx.x;                       // 0 .. 511
    float pos = (float)(KK - 1 - j);
    const float c2 = -13.287712379549449f / 512.0f;
    float invf = ex2_approx(c2 * (float)i);
    float ang  = pos * invf;
    float k = rintf(ang * 0.15915494309189535f);
    float a = fmaf(k, -6.2831854820251465f, ang);
    a = fmaf(k, 1.7484555e-7f, a);
    float s, cc;
    __sincosf(a, &s, &cc);
    pe[(size_t)j * HID + i]       = f2tff(s);
    pe[(size_t)j * HID + 512 + i] = f2tff(cc);
}

// ---------------- tf32 SGEMM: C[M,1024] = A[M,1024]*B[1024,1024] ------------
// Inputs pre-rounded to tf32 (stored as fp32); no cvt in inner loop.
constexpr int GA_STRIDE = 20;
constexpr int GB_STRIDE = 136;
constexpr int GA_BUF = 128 * GA_STRIDE;   // 2560
constexpr int GB_BUF = 16 * GB_STRIDE;    // 2176
constexpr int GEMM_SMEM_BYTES = 3 * (GA_BUF + GB_BUF) * 4;   // 56,832 B

__global__ __launch_bounds__(256, 2)
void sgemm_tf32(const float* __restrict__ A, const float* __restrict__ B,
                float* __restrict__ C, int roundC)
{
    extern __shared__ float gsm[];
    float* sA = gsm;                  // 3 x [128][20]
    float* sB = gsm + 3 * GA_BUF;     // 3 x [16][136]
    const int tid = threadIdx.x;
    const int lane = tid & 31, wid = tid >> 5;
    const int g = lane >> 2, tg = lane & 3;
    const int wm = (wid & 1) * 64, wn = (wid >> 1) * 32;
    const int row0 = blockIdx.y * 128, col0 = blockIdx.x * 128;

    const int af4a = tid,        af4b = tid + 256;
    const int ar_a = af4a >> 2,  ac_a = (af4a & 3) << 2;
    const int ar_b = af4b >> 2,  ac_b = (af4b & 3) << 2;
    const int br_a = af4a >> 5,  bc_a = (af4a & 31) << 2;
    const int br_b = af4b >> 5,  bc_b = (af4b & 31) << 2;

    auto issue = [&](int buf, int k0) {
        float* a = sA + buf * GA_BUF;
        float* bfp = sB + buf * GB_BUF;
        cpa16(&a[ar_a * GA_STRIDE + ac_a], &A[(size_t)(row0 + ar_a) * 1024 + k0 + ac_a]);
        cpa16(&a[ar_b * GA_STRIDE + ac_b], &A[(size_t)(row0 + ar_b) * 1024 + k0 + ac_b]);
        cpa16(&bfp[br_a * GB_STRIDE + bc_a], &B[(size_t)(k0 + br_a) * 1024 + col0 + bc_a]);
        cpa16(&bfp[br_b * GB_STRIDE + bc_b], &B[(size_t)(k0 + br_b) * 1024 + col0 + bc_b]);
    };

    issue(0, 0);
    CP_COMMIT();
    issue(1, 16);
    CP_COMMIT();

    float4 acc[4][4];
#pragma unroll
    for (int i = 0; i < 4; i++)
#pragma unroll
        for (int j = 0; j < 4; j++) acc[i][j] = make_float4(0.f, 0.f, 0.f, 0.f);

    for (int it = 0; it < 64; it++) {
        CP_WAIT(1);
        __syncthreads();
        if (it + 2 < 64) issue((it + 2) % 3, (it + 2) * 16);
        CP_COMMIT();

        const float* a = sA + (it % 3) * GA_BUF;
        const float* bs = sB + (it % 3) * GB_BUF;
#pragma unroll
        for (int kk = 0; kk < 16; kk += 8) {
            uint32_t af[4][4], bf[4][2];
#pragma unroll
            for (int mf = 0; mf < 4; mf++) {
                int m = wm + mf * 16;
                af[mf][0] = __float_as_uint(a[(m + g) * GA_STRIDE + kk + tg]);
                af[mf][1] = __float_as_uint(a[(m + g + 8) * GA_STRIDE + kk + tg]);
                af[mf][2] = __float_as_uint(a[(m + g) * GA_STRIDE + kk + tg + 4]);
                af[mf][3] = __float_as_uint(a[(m + g + 8) * GA_STRIDE + kk + tg + 4]);
            }
#pragma unroll
            for (int nf = 0; nf < 4; nf++) {
                int n = wn + nf * 8;
                bf[nf][0] = __float_as_uint(bs[(kk + tg) * GB_STRIDE + n + g]);
                bf[nf][1] = __float_as_uint(bs[(kk + tg + 4) * GB_STRIDE + n + g]);
            }
#pragma unroll
            for (int mf = 0; mf < 4; mf++)
#pragma unroll
                for (int nf = 0; nf < 4; nf++)
                    mma_tf32(acc[mf][nf], af[mf], bf[nf]);
        }
    }
    if (roundC) {
#pragma unroll
        for (int mf = 0; mf < 4; mf++)
#pragma unroll
            for (int nf = 0; nf < 4; nf++) {
                int r = row0 + wm + mf * 16 + g;
                int c = col0 + wn + nf * 8 + 2 * tg;
                *(float2*)&C[(size_t)r * 1024 + c] =
                    make_float2(f2tff(acc[mf][nf].x), f2tff(acc[mf][nf].y));
                *(float2*)&C[(size_t)(r + 8) * 1024 + c] =
                    make_float2(f2tff(acc[mf][nf].z), f2tff(acc[mf][nf].w));
            }
    } else {
#pragma unroll
        for (int mf = 0; mf < 4; mf++)
#pragma unroll
            for (int nf = 0; nf < 4; nf++) {
                int r = row0 + wm + mf * 16 + g;
                int c = col0 + wn + nf * 8 + 2 * tg;
                *(float2*)&C[(size_t)r * 1024 + c] = make_float2(acc[mf][nf].x, acc[mf][nf].y);
                *(float2*)&C[(size_t)(r + 8) * 1024 + c] = make_float2(acc[mf][nf].z, acc[mf][nf].w);
            }
    }
}

// ---------------- fused relative attention (tf32 mma, banded BD, async) -----
// grid: (Q/64, B*H); 256 threads, 8 warps.
// bd1 folded into BD spill; lf dropped (1e-8*lf term is <=1e-8 relative).
constexpr int AT_SQ  = 0;       // Qw^T [64 d][72]  tf32
constexpr int AT_SK  = 4608;    // K    [64 k][68]  tf32 (pre-rounded fp32)
constexpr int AT_SV  = 8960;    // V    [64 k][72]  tf32
constexpr int AT_SR  = 13568;   // Rel  [128 j][68] tf32 / BD^T f32 (alias)
constexpr int AT_SPT = 22272;   // P^T  [64 k][72]  tf32
constexpr int AT_SB1 = 26880;   // bd1 [128] f32
constexpr int AT_SDL = 27136;   // dl   [64]  f32
constexpr int AT_SRM = 27200;   // lm red [4][64]
constexpr int AT_SIV = 27456;   // inv  [64]
constexpr int AT_TOT = 27520;
constexpr int ATTN_SMEM_BYTES = AT_TOT * 4;     // 110,080 B -> 2 CTAs/SM

__global__ __launch_bounds__(256, 2)
void attn_tf32(const float* __restrict__ Qp, const float* __restrict__ Kp,
               const float* __restrict__ Vp, const float* __restrict__ Rel,
               const float* __restrict__ rwb, const float* __restrict__ rrb,
               const float* __restrict__ span, float* __restrict__ Out)
{
    extern __shared__ float sm[];
    uint32_t* uQ  = (uint32_t*)(sm + AT_SQ);
    uint32_t* uK  = (uint32_t*)(sm + AT_SK);
    uint32_t* uV  = (uint32_t*)(sm + AT_SV);
    uint32_t* uR  = (uint32_t*)(sm + AT_SR);
    float*   sBDT = sm + AT_SR;                  // alias over Rel
    uint32_t* uPT = (uint32_t*)(sm + AT_SPT);
    float* sB1 = sm + AT_SB1;
    float* sDl = sm + AT_SDL;
    float* sRM = sm + AT_SRM;
    float* sIv = sm + AT_SIV;

    const int tid = threadIdx.x;
    const int lane = tid & 31, wid = tid >> 5;
    const int g = lane >> 2, tg = lane & 3;
    const int wm = wid & 3;            // key/d strip (x16) for AD / PV
    const int wn = wid >> 2;           // q half (x32)
    // BD band assignment: strip sB = 7-wid aligns bd q-range with sf q-range
    const int sB  = 7 - wid;
    const int nf_lo = max(0, 6 - 2 * sB);
    const int nf_hi = min(7, 15 - 2 * sB);
    const int lo2 = min(nf_lo, wn * 4);
    const int hi2 = max(nf_hi, wn * 4 + 3);
    // big-work CTAs launch first
    const int qt = (int)gridDim.x - 1 - (int)blockIdx.x;
    const int q0 = qt * 64;
    const int b = blockIdx.y >> 4, h = blockIdx.y & 15;
    const float spanv = span[h];

    // staging issuers (cp.async.ca — L1-allocating; all operands pre-rounded)
    auto issueK = [&](int k0s) {
#pragma unroll
        for (int idx = tid; idx < 1024; idx += 256) {
            int kk = idx >> 4, d4 = (idx & 15) << 2;
            cpa16ca(&uK[kk * 68 + d4],
                    &Kp[((size_t)(b * KK + k0s + kk)) * HID + h * 64 + d4]);
        }
    };
    auto issueV = [&](int k0s) {
#pragma unroll
        for (int idx = tid; idx < 1024; idx += 256) {
            int kk = idx >> 4, d4 = (idx & 15) << 2;
            cpa16ca(&uV[kk * 72 + d4],
                    &Vp[((size_t)(b * KK + k0s + kk)) * HID + h * 64 + d4]);
        }
    };
    auto issueR = [&](int k0s) {
        int jb = k0s + (QQ - 1) - (q0 + 63);
#pragma unroll
        for (int idx = tid; idx < 2048; idx += 256) {
            int jj = idx >> 4, d4 = (idx & 15) << 2;
            int j = jb + jj;
            bool ok = (j < KK);
            cpa16ca_z(&uR[jj * 68 + d4],
                      ok ? &Rel[(size_t)j * HID + h * 64 + d4] : (const float*)Rel,
                      ok ? 16 : 0);
        }
    };

    if (tid < 64) sDl[tid] = rrb[h * 64 + tid] - rwb[h * 64 + tid];

    // prologue: K(0), R(0) in flight
    issueK(0); CP_COMMIT();
    issueR(0); CP_COMMIT();

    // stage Qw^T = (q + r_w_bias)^T, tf32 (once per CTA)
    for (int idx = tid; idx < 1024; idx += 256) {
        int qq = idx >> 4, d4 = (idx & 15) << 2;
        float4 qv = *(const float4*)&Qp[((size_t)(b * QQ + q0 + qq)) * HID + h * 64 + d4];
        float4 wb = *(const float4*)&rwb[h * 64 + d4];
        uQ[(d4 + 0) * 72 + qq] = f2tf(qv.x + wb.x);
        uQ[(d4 + 1) * 72 + qq] = f2tf(qv.y + wb.y);
        uQ[(d4 + 2) * 72 + qq] = f2tf(qv.z + wb.z);
        uQ[(d4 + 3) * 72 + qq] = f2tf(qv.w + wb.w);
    }

    float4 o[4];
#pragma unroll
    for (int i = 0; i < 4; i++) o[i] = make_float4(0.f, 0.f, 0.f, 0.f);
    float lmp[8];
#pragma unroll
    for (int i = 0; i < 8; i++) lmp[i] = 0.f;

    const int ntiles = 33 + qt;
    for (int t = 0; t < ntiles; t++) {
        const int k0 = t * 64;
        const int k0n = min(k0 + 64, KK - 64);  // clamped prefetch target

        __syncthreads();               // PV(t-1) complete; uV free (Q stage at t=0)
        issueV(k0); CP_COMMIT();       // groups: [K(t), R(t), V(t)]
        CP_WAIT(1);                    // K(t), R(t) arrived (this thread)
        __syncthreads();               // ... visible to all threads

        // bd1[j] = sum_d Rel[j][d] * dl[d]  (128 threads, full dot)
        if (tid < 128) {
            const float* rr = (const float*)&uR[tid * 68];
            float s = 0.f;
#pragma unroll
            for (int d4 = 0; d4 < 64; d4 += 4) {
                float4 r4 = *(const float4*)&rr[d4];
                float4 dl4 = *(const float4*)&sDl[d4];
                s += r4.x * dl4.x + r4.y * dl4.y + r4.z * dl4.z + r4.w * dl4.w;
            }
            sB1[tid] = s;
        }

        // AD^T + banded BD^T mma (shared B-operand = Qw^T)
        float4 sf[4];
        float4 bdf[8];
#pragma unroll
        for (int i = 0; i < 4; i++) sf[i] = make_float4(0.f, 0.f, 0.f, 0.f);
#pragma unroll
        for (int i = 0; i < 8; i++) bdf[i] = make_float4(0.f, 0.f, 0.f, 0.f);
#pragma unroll
        for (int ks = 0; ks < 64; ks += 8) {
            uint32_t bq[8][2];
#pragma unroll
            for (int nf = 0; nf < 8; nf++) {
                if (nf >= lo2 && nf <= hi2) {
                    int n = nf * 8 + g;
                    bq[nf][0] = uQ[(ks + tg) * 72 + n];
                    bq[nf][1] = uQ[(ks + tg + 4) * 72 + n];
                }
            }
            uint32_t ak[4], ar[4];
            {
                int m = wm * 16;
                ak[0] = uK[(m + g) * 68 + ks + tg];
                ak[1] = uK[(m + g + 8) * 68 + ks + tg];
                ak[2] = uK[(m + g) * 68 + ks + tg + 4];
                ak[3] = uK[(m + g + 8) * 68 + ks + tg + 4];
            }
            {
                int m = sB * 16;
                ar[0] = uR[(m + g) * 68 + ks + tg];
                ar[1] = uR[(m + g + 8) * 68 + ks + tg];
                ar[2] = uR[(m + g) * 68 + ks + tg + 4];
                ar[3] = uR[(m + g + 8) * 68 + ks + tg + 4];
            }
#pragma unroll
            for (int nf = 0; nf < 4; nf++)
                mma_tf32(sf[nf], ak, bq[wn * 4 + nf]);
#pragma unroll
            for (int nf = 0; nf < 8; nf++)
                if (nf >= nf_lo && nf <= nf_hi)
                    mma_tf32(bdf[nf], ar, bq[nf]);
        }
        __syncthreads();               // all uK/uR mma+bd1 reads done

        // spill banded BD^T (+bd1[j] folded) into sBDT; prefetch K(t+1)
        {
            int j = sB * 16 + g;
            float b1a = sB1[j], b1b = sB1[j + 8];
#pragma unroll
            for (int nf = 0; nf < 8; nf++) {
                if (nf >= nf_lo && nf <= nf_hi) {
                    int q = nf * 8 + 2 * tg;
                    *(float2*)&sBDT[j * 68 + q] =
                        make_float2(bdf[nf].x + b1a, bdf[nf].y + b1a);
                    *(float2*)&sBDT[(j + 8) * 68 + q] =
                        make_float2(bdf[nf].z + b1b, bdf[nf].w + b1b);
                }
            }
        }
        issueK(k0n); CP_COMMIT();      // groups: [V(t)?, K(t+1)]
        __syncthreads();               // sBDT visible

        // softmax on in-register S^T (exp2 with folded log2e/64 scale)
        const float ESC = 0.022542120622634243f;  // log2(e) / 64
        float mk2[2];
#pragma unroll
        for (int half = 0; half < 2; half++) {
            int k = k0 + wm * 16 + g + half * 8;
            mk2[half] = (k >= MM)
                ? fminf(fmaxf(((float)(k - MM) + spanv * (float)QQ) * (1.0f / 33.0f), 0.0f), 1.0f)
                : 1.0f;
        }
        const bool lastT = (t == ntiles - 1);
#pragma unroll
        for (int nf = 0; nf < 4; nf++) {
            float sv[4] = {sf[nf].x, sf[nf].y, sf[nf].z, sf[nf].w};
            uint32_t pt[4];
#pragma unroll
            for (int e = 0; e < 4; e++) {
                int half = e >> 1, p = e & 1;
                int key = wm * 16 + g + half * 8;
                int q = wn * 32 + nf * 8 + 2 * tg + p;
                int j = key + 63 - q;
                float val = (sv[e] + sBDT[j * 68 + q]) * ESC;
                float ex = ex2_approx(val);
                if (lastT && (k0 + key > MM + q0 + q)) ex = 0.f;
                float em = ex * mk2[half];
                lmp[nf * 2 + p] += em;
                pt[e] = f2tf(em);
            }
            int q = wn * 32 + nf * 8 + 2 * tg;
            int key = wm * 16 + g;
            *(uint2*)&uPT[key * 72 + q]       = make_uint2(pt[0], pt[1]);
            *(uint2*)&uPT[(key + 8) * 72 + q] = make_uint2(pt[2], pt[3]);
        }
        CP_WAIT(1);                    // V(t) arrived (oldest of [V(t), K(t+1)])
        __syncthreads();               // uPT + all threads' V visible

        // O^T += V^T * P^T; prefetch Rel(t+1) into uR (dead until next mma)
        issueR(k0n); CP_COMMIT();      // groups: [K(t+1), R(t+1)]
#pragma unroll
        for (int ks = 0; ks < 64; ks += 8) {
            uint32_t av[4];
            int m = wm * 16;
            av[0] = uV[(ks + tg) * 72 + m + g];
            av[1] = uV[(ks + tg) * 72 + m + g + 8];
            av[2] = uV[(ks + tg + 4) * 72 + m + g];
            av[3] = uV[(ks + tg + 4) * 72 + m + g + 8];
            uint32_t bp[4][2];
#pragma unroll
            for (int nf = 0; nf < 4; nf++) {
                int n = wn * 32 + nf * 8 + g;
                bp[nf][0] = uPT[(ks + tg) * 72 + n];
                bp[nf][1] = uPT[(ks + tg + 4) * 72 + n];
            }
#pragma unroll
            for (int nf = 0; nf < 4; nf++)
                mma_tf32(o[nf], av, bp[nf]);
        }
    }
    CP_WAIT(0);                        // drain tail prefetches (dead data)

    // reduce lm over g lanes
#pragma unroll
    for (int s = 0; s < 8; s++) {
#pragma unroll
        for (int off = 4; off <= 16; off <<= 1)
            lmp[s] += __shfl_xor_sync(0xffffffffu, lmp[s], off);
    }
    if (g == 0) {
#pragma unroll
        for (int nf = 0; nf < 4; nf++) {
            int q = wn * 32 + nf * 8 + 2 * tg;
            *(float2*)&sRM[wm * 64 + q] = make_float2(lmp[nf * 2], lmp[nf * 2 + 1]);
        }
    }
    __syncthreads();
    if (tid < 64) {
        float lm = sRM[tid] + sRM[64 + tid] + sRM[128 + tid] + sRM[192 + tid];
        sIv[tid] = 1.0f / lm;      // 1e-8*lf term is <=1e-8 relative; dropped
    }
    __syncthreads();

    // write output (tf32-rounded — feeds final GEMM's A operand)
#pragma unroll
    for (int nf = 0; nf < 4; nf++) {
        int q = wn * 32 + nf * 8 + 2 * tg;
        int d = wm * 16 + g;
        float i0 = sIv[q], i1 = sIv[q + 1];
        size_t base0 = ((size_t)(b * QQ + q0 + q)) * HID + h * 64;
        size_t base1 = base0 + HID;
        Out[base0 + d]     = f2tff(o[nf].x * i0);
        Out[base1 + d]     = f2tff(o[nf].y * i1);
        Out[base0 + d + 8] = f2tff(o[nf].z * i0);
        Out[base1 + d + 8] = f2tff(o[nf].w * i1);
    }
}

// ---------------- launch -----------------------------------------------------
extern "C" void kernel_launch(void* const* d_in, const int* in_sizes, int n_in,
                              void* d_out, int out_size)
{
    const float* query     = (const float*)d_in[0];
    const float* memory    = (const float*)d_in[1];
    const float* Wq        = (const float*)d_in[2];
    const float* Wk        = (const float*)d_in[3];
    const float* Wv        = (const float*)d_in[4];
    const float* Wo        = (const float*)d_in[5];
    const float* Wr        = (const float*)d_in[6];
    const float* gamma_mem = (const float*)d_in[7];
    const float* beta_mem  = (const float*)d_in[8];
    const float* gamma_q   = (const float*)d_in[9];
    const float* beta_q    = (const float*)d_in[10];
    const float* rwb       = (const float*)d_in[11];
    const float* rrb       = (const float*)d_in[12];
    const float* span      = (const float*)d_in[13];
    float* out = (float*)d_out;

    float *kvln, *qln, *pe, *Qp, *Kp, *Vp, *Rel, *attn, *Wtf;
    cudaGetSymbolAddress((void**)&kvln, g_kvln);
    cudaGetSymbolAddress((void**)&qln,  g_qln);
    cudaGetSymbolAddress((void**)&pe,   g_pe);
    cudaGetSymbolAddress((void**)&Qp,   g_Qp);
    cudaGetSymbolAddress((void**)&Kp,   g_Kp);
    cudaGetSymbolAddress((void**)&Vp,   g_Vp);
    cudaGetSymbolAddress((void**)&Rel,  g_Rel);
    cudaGetSymbolAddress((void**)&attn, g_attn);
    cudaGetSymbolAddress((void**)&Wtf,  g_Wtf);

    float* Wq_t = Wtf + 0 * (size_t)HID * HID;
    float* Wk_t = Wtf + 1 * (size_t)HID * HID;
    float* Wv_t = Wtf + 2 * (size_t)HID * HID;
    float* Wr_t = Wtf + 3 * (size_t)HID * HID;
    float* Wo_t = Wtf + 4 * (size_t)HID * HID;

    cudaFuncSetAttribute(attn_tf32, cudaFuncAttributeMaxDynamicSharedMemorySize,
                         ATTN_SMEM_BYTES);
    cudaFuncSetAttribute(sgemm_tf32, cudaFuncAttributeMaxDynamicSharedMemorySize,
                         GEMM_SMEM_BYTES);

    // Fork/join side stream (created once at first, uncaptured, call).
    static cudaStream_t sSide = nullptr;
    static cudaEvent_t  eFork = nullptr, eJoin = nullptr;
    if (sSide == nullptr) {
        cudaStreamCreateWithFlags(&sSide, cudaStreamNonBlocking);
        cudaEventCreateWithFlags(&eFork, cudaEventDisableTiming);
        cudaEventCreateWithFlags(&eJoin, cudaEventDisableTiming);
    }
    cudaStream_t s0 = 0;

    const int W4 = (HID * HID) / 4 / 256;

    // fork
    cudaEventRecord(eFork, s0);
    cudaStreamWaitEvent(sSide, eFork, 0);

    // branch A (side): ln_q, posemb, Wq/Wr/Wo roundings, Qp-gemm, Rel-gemm
    ln_q_kernel <<<BB * QQ, 256, 0, sSide>>>(query, gamma_q, beta_q, qln);
    posemb_kernel<<<KK, 512, 0, sSide>>>(pe);
    round_tf32_kernel<<<W4, 256, 0, sSide>>>(Wq, Wq_t);
    round_tf32_kernel<<<W4, 256, 0, sSide>>>(Wr, Wr_t);
    round_tf32_kernel<<<W4, 256, 0, sSide>>>(Wo, Wo_t);
    sgemm_tf32<<<dim3(8, (BB * QQ) / 128), 256, GEMM_SMEM_BYTES, sSide>>>(qln, Wq_t, Qp, 1);
    sgemm_tf32<<<dim3(8, KK / 128),        256, GEMM_SMEM_BYTES, sSide>>>(pe,  Wr_t, Rel, 1);
    cudaEventRecord(eJoin, sSide);

    // branch 0 (main): ln_kv, Wk/Wv roundings, Kp-gemm, Vp-gemm
    ln_kv_kernel<<<BB * KK, 256, 0, s0>>>(memory, query, gamma_mem, beta_mem, kvln);
    round_tf32_kernel<<<W4, 256, 0, s0>>>(Wk, Wk_t);
    round_tf32_kernel<<<W4, 256, 0, s0>>>(Wv, Wv_t);
    sgemm_tf32<<<dim3(8, (BB * KK) / 128), 256, GEMM_SMEM_BYTES, s0>>>(kvln, Wk_t, Kp, 1);
    sgemm_tf32<<<dim3(8, (BB * KK) / 128), 256, GEMM_SMEM_BYTES, s0>>>(kvln, Wv_t, Vp, 1);

    // join
    cudaStreamWaitEvent(s0, eJoin, 0);

    attn_tf32<<<dim3(QQ / 64, BB * HH), 256, ATTN_SMEM_BYTES, s0>>>(
        Qp, Kp, Vp, Rel, rwb, rrb, span, attn);

    sgemm_tf32<<<dim3(8, (BB * QQ) / 128), 256, GEMM_SMEM_BYTES, s0>>>(attn, Wo_t, out, 0);
}